// round 12
// baseline (speedup 1.0000x reference)
#include <cuda_runtime.h>

#define NGRID   41088
#define PMAX    404
#define MDIM    192
#define KR      192
#define KF      96
#define BCN     1024
#define TWO_PI_F 6.28318530717958647692f

typedef unsigned long long u64;
typedef unsigned int u32;

// Pre-folded stage-A output: (re,im) pairs, layout [m][kf][bc], kf in [0,96)
__device__ u64 g_rip[(size_t)MDIM * KF * BCN];   // A+ = A[k] + A[191-k]
__device__ u64 g_rim[(size_t)MDIM * KF * BCN];   // A- = A[k] - A[191-k]
// Stage-B staging: (re,im) pairs, layout [m][l][bc]
__device__ u64 g_st[(size_t)MDIM * MDIM * BCN];

__device__ __forceinline__ u64 ffma2(u64 a, u64 b, u64 c) {
    u64 d; asm("fma.rn.f32x2 %0,%1,%2,%3;" : "=l"(d) : "l"(a), "l"(b), "l"(c)); return d;
}
__device__ __forceinline__ u64 fmul2(u64 a, u64 b) {
    u64 d; asm("mul.rn.f32x2 %0,%1,%2;" : "=l"(d) : "l"(a), "l"(b)); return d;
}
__device__ __forceinline__ u64 fadd2(u64 a, u64 b) {
    u64 d; asm("add.rn.f32x2 %0,%1,%2;" : "=l"(d) : "l"(a), "l"(b)); return d;
}
__device__ __forceinline__ u64 pk2(float lo, float hi) {
    u64 r; asm("mov.b64 %0,{%1,%2};" : "=l"(r) : "f"(lo), "f"(hi)); return r;
}
__device__ __forceinline__ void lds2(u64& a, u64& b, u32 addr) {
    asm volatile("ld.shared.v2.u64 {%0,%1},[%2];" : "=l"(a), "=l"(b) : "r"(addr));
}
__device__ __forceinline__ float4 lds4f(u32 addr) {
    float4 v;
    asm volatile("ld.shared.v4.f32 {%0,%1,%2,%3},[%4];"
                 : "=f"(v.x), "=f"(v.y), "=f"(v.z), "=f"(v.w) : "r"(addr));
    return v;
}
__device__ __forceinline__ void sts4(u32 addr, float a, float b, float c, float d) {
    asm volatile("st.shared.v4.f32 [%0],{%1,%2,%3,%4};" :: "r"(addr), "f"(a), "f"(b), "f"(c), "f"(d));
}
__device__ __forceinline__ void sts2(u32 addr, float a, float b) {
    asm volatile("st.shared.v2.f32 [%0],{%1,%2};" :: "r"(addr), "f"(a), "f"(b));
}
__device__ __forceinline__ void sts1(u32 addr, float a) {
    asm volatile("st.shared.f32 [%0],%1;" :: "r"(addr), "f"(a));
}
__device__ __forceinline__ u32 s2u(const void* p) {
    u32 a; asm("{.reg .u64 t; cvta.to.shared.u64 t,%1; cvt.u32.u64 %0,t;}" : "=r"(a) : "l"(p)); return a;
}
__device__ __forceinline__ void cpa16(u32 dst, const void* src, int bytes) {
    asm volatile("cp.async.cg.shared.global [%0],[%1],16,%2;" :: "r"(dst), "l"(src), "r"(bytes));
}
__device__ __forceinline__ void cpcommit() { asm volatile("cp.async.commit_group;"); }
__device__ __forceinline__ void cpwait0()  { asm volatile("cp.async.wait_group 0;"); }

// ---------------------------------------------------------------------------
// Stage A: folded per-ring DFT on ring PAIRS (k1, 191-k1).
// grid = (16 bc-tiles of 64, 96 pairs big-first, 3 m-tiles of 64), 256 thr.
// 2-D warp tiling: warp (mw 0..3, bw 0..1) owns 16m x 32bc x 2rings, so each
// warp touches half the x tile and a quarter of the basis tile:
// 6 smem wavefronts per 32 FFMA2 (was 10 with 1-D warps).
// Lane (lm = lane>>3, lb = lane&7): m = mw*16+lm*4+j,
// bc = bw*32 + 2lb {+0,+1} and bw*32+16 + 2lb {+0,+1}.
// ---------------------------------------------------------------------------
extern "C" __global__ void __launch_bounds__(256, 2)
sht_stageA(const float* __restrict__ x,
           const float* __restrict__ cosb,
           const float* __restrict__ sinb)
{
    __shared__ __align__(16) unsigned char sm[2 * 16 * 512 + 2 * 16 * 1024]; // 49152
    const int t   = threadIdx.x;
    const int bc0 = blockIdx.x * 64;
    const int k1  = 95 - blockIdx.y;        // big rings first (k1=95: nlon 404)
    const int m0  = blockIdx.z * 64;

    const int nlon  = 24 + 4 * k1;
    const int slon1 = 2 * k1 * k1 + 22 * k1;
    const int q2    = k1 + 1;               // = 192 - k2, k2 = 96 + blockIdx.y
    const int slon2 = NGRID - (2 * q2 * q2 + 22 * q2);
    int mmax = 12 + 2 * k1;
    if (mmax > MDIM - 1) mmax = MDIM - 1;   // identical for both rings of pair
    if (m0 > mmax) return;                  // inactive m-tile: never read downstream
    const int half   = nlon >> 1;
    const int ntiles = (half + 16) >> 4;    // ceil((half+1)/16)

    const u32 sb = s2u(sm);
    const u32 CS = sb;                      // [buf][16q][64 m u64], row 512 B
    const u32 XS = sb + 16384;              // [buf][16q][2 ring][64 bc u64], row 1024 B

    // staging roles (unchanged layouts)
    const int ppb = t >> 4, mq = (t & 15) * 4;   // basis: 1 q-row, 4 m
    const int bcr = t >> 1, pq = (t & 1) * 8;    // x: 1 (ring,bc)-row, 8 q
    const int ring = bcr >> 6, bcl = bcr & 63;

    // compute roles: warp (mw, bw); lane (lm, lb)
    const int w = t >> 5, lane = t & 31;
    const int mw = w & 3, bw = w >> 2;
    const int lm = lane >> 3, lb = lane & 7;

    const float* xrow  = x + (size_t)(bc0 + bcl) * NGRID + (ring ? slon2 : slon1);
    const float* cbase = cosb + ((size_t)k1 * PMAX) * MDIM + m0 + mq;
    const float* sbase = sinb + ((size_t)k1 * PMAX) * MDIM + m0 + mq;

    u64 acc0[4][4], acc1[4][4];
#pragma unroll
    for (int j = 0; j < 4; j++)
#pragma unroll
        for (int i = 0; i < 4; i++) { acc0[j][i] = 0ull; acc1[j][i] = 0ull; }

    float4 c4, s4, fw0, fw1, bw0, bw1;
    float ps0, ps1;
    int p0s;
    const float4 z4 = make_float4(0.f, 0.f, 0.f, 0.f);

    auto prefetch = [&](int p0) {
        p0s = p0;
        int p = p0 + ppb;                   // p <= 207 < PMAX: in-bounds
        c4 = *(const float4*)(cbase + (size_t)p * MDIM);
        s4 = *(const float4*)(sbase + (size_t)p * MDIM);
        int q0 = p0 + pq;
        if (q0 <= half) {
            fw0 = *(const float4*)(xrow + q0);
            bw0 = *(const float4*)(xrow + nlon - q0 - 4);
            ps0 = (q0 >= 1) ? xrow[nlon - q0] : 0.f;
        } else { fw0 = z4; bw0 = z4; ps0 = 0.f; }
        int q1 = q0 + 4;
        if (q1 <= half) {
            fw1 = *(const float4*)(xrow + q1);
            bw1 = *(const float4*)(xrow + nlon - q1 - 4);
            ps1 = xrow[nlon - q1];
        } else { fw1 = z4; bw1 = z4; ps1 = 0.f; }
    };

    auto fold_emit = [&](u32 a, float4 f, float4 b, float ps, int qv) {
        float fr[4] = {f.x, f.y, f.z, f.w};
        float pr[4] = {ps, b.w, b.z, b.y};
#pragma unroll
        for (int i = 0; i < 4; i++) {
            int q = qv + i;
            bool valid = q <= half;
            bool spec  = (q == 0) || (q == half);
            float pl = valid ? (spec ? fr[i] : fr[i] + pr[i]) : 0.f;
            float mi = (valid && !spec) ? fr[i] - pr[i] : 0.f;
            sts2(a + i * 1024, pl, mi);
        }
    };

    auto store_tile = [&](int buf) {
        u32 cs = CS + buf * 8192 + ppb * 512 + mq * 8;
        sts4(cs,      c4.x, s4.x, c4.y, s4.y);
        sts4(cs + 16, c4.z, s4.z, c4.w, s4.w);
        u32 xa = XS + buf * 16384 + pq * 1024 + ring * 512 + bcl * 8;
        int q0 = p0s + pq;
        fold_emit(xa,        fw0, bw0, ps0, q0);
        fold_emit(xa + 4096, fw1, bw1, ps1, q0 + 4);
    };

    auto compute = [&](int buf) {
        u32 cs = CS + buf * 8192 + mw * 128 + lm * 32;
        u32 xs = XS + buf * 16384 + bw * 256 + lb * 16;
#pragma unroll
        for (int pp = 0; pp < 16; ++pp) {
            u64 b0, b1, b2, b3;
            lds2(b0, b1, cs + pp * 512);
            lds2(b2, b3, cs + pp * 512 + 16);
            u64 v[4], u[4];
            lds2(v[0], v[1], xs + pp * 1024);          // ring0 bc bw32+{2lb,2lb+1}
            lds2(v[2], v[3], xs + pp * 1024 + 128);    // ring0 bc bw32+16+{2lb,2lb+1}
            lds2(u[0], u[1], xs + pp * 1024 + 512);    // ring1 bc bw32+{2lb,2lb+1}
            lds2(u[2], u[3], xs + pp * 1024 + 640);    // ring1 bc bw32+16+{2lb,2lb+1}
#pragma unroll
            for (int i = 0; i < 4; i++) {
                acc0[0][i] = ffma2(b0, v[i], acc0[0][i]);
                acc0[1][i] = ffma2(b1, v[i], acc0[1][i]);
                acc0[2][i] = ffma2(b2, v[i], acc0[2][i]);
                acc0[3][i] = ffma2(b3, v[i], acc0[3][i]);
                acc1[0][i] = ffma2(b0, u[i], acc1[0][i]);
                acc1[1][i] = ffma2(b1, u[i], acc1[1][i]);
                acc1[2][i] = ffma2(b2, u[i], acc1[2][i]);
                acc1[3][i] = ffma2(b3, u[i], acc1[3][i]);
            }
        }
    };

    prefetch(0);
    store_tile(0);
    __syncthreads();
    for (int ti = 0; ti < ntiles; ++ti) {
        bool nx = (ti + 1) < ntiles;
        if (nx) prefetch((ti + 1) << 4);
        compute(ti & 1);
        if (nx) store_tile((ti + 1) & 1);
        __syncthreads();
    }

    // epilogue: fold across hemisphere pair, scale by 2*pi, STG.128.
    // thread bc = bw*32 + 2lb {+0,+1} (acc[.][0..1]); +16 (acc[.][2..3]).
    const u64 tp2  = pk2(TWO_PI_F, TWO_PI_F);
    const u64 NEG1 = pk2(-1.f, -1.f);
#pragma unroll
    for (int j = 0; j < 4; j++) {
        size_t base = ((size_t)(m0 + mw * 16 + lm * 4 + j) * KF + k1) * BCN
                      + bc0 + bw * 32 + 2 * lb;
        u64* op = g_rip + base;
        u64* om = g_rim + base;
        ulonglong2 wp0, wp1, wm0, wm1;
        wp0.x = fmul2(fadd2(acc0[j][0], acc1[j][0]), tp2);
        wp0.y = fmul2(fadd2(acc0[j][1], acc1[j][1]), tp2);
        wp1.x = fmul2(fadd2(acc0[j][2], acc1[j][2]), tp2);
        wp1.y = fmul2(fadd2(acc0[j][3], acc1[j][3]), tp2);
        wm0.x = fmul2(ffma2(acc1[j][0], NEG1, acc0[j][0]), tp2);
        wm0.y = fmul2(ffma2(acc1[j][1], NEG1, acc0[j][1]), tp2);
        wm1.x = fmul2(ffma2(acc1[j][2], NEG1, acc0[j][2]), tp2);
        wm1.y = fmul2(ffma2(acc1[j][3], NEG1, acc0[j][3]), tp2);
        *(ulonglong2*)op        = wp0;
        *(ulonglong2*)(op + 16) = wp1;
        *(ulonglong2*)om        = wm0;
        *(ulonglong2*)(om + 16) = wm1;
    }
}

// ---------------------------------------------------------------------------
// Stage B: per-m GEMM on pre-folded operands, parity-coherent warps.
//   weight[m,l,k] = (-1)^(l+m) weight[m,l,191-k]
//   st[m,l,bc] = sum_{k in [klo,95]} W[m,l,k] * ( (l+m) even ? A+[k] : A-[k] )
// grid = (16 bc-tiles of 64, 3 l-tiles of 64, 192 m), block = 128.
// ---------------------------------------------------------------------------
extern "C" __global__ void __launch_bounds__(128, 4)
sht_stageB(const float* __restrict__ weight)
{
    __shared__ __align__(16) unsigned char sm[4 * 16 * 512 + 2 * 16 * 256];  // 40960
    const int t   = threadIdx.x;
    const int bc0 = blockIdx.x * 64;
    const int l0  = blockIdx.y * 64;
    const int m   = blockIdx.z;
    if (l0 + 63 < m) return;                // zero triangle: handled by transpose

    const int klo = (m <= 12) ? 0 : ((m - 11) >> 1);   // klo <= 90 < 96
    const int kb0 = klo & ~15;
    const int nkt = ((95 - kb0) >> 4) + 1;  // tiles cover [kb0, 95] exactly

    const u32 sb  = s2u(sm);
    const u32 APS = sb;                     // A+ : [buf][16k][64bc u64], row 512 B
    const u32 AMS = sb + 16384;             // A-
    const u32 WS  = sb + 32768;             // W  : [buf][16k][2 par][32 lc] f32, row 256 B

    // staging roles
    const int lr = t >> 1, kq = (t & 1) * 8;       // W: 1 l-row, 8 k
    const int wpar = (lr + m) & 1, wlc = lr >> 1;

    // compute roles
    const int w = t >> 5, lane = t & 31;
    const int pw  = w & 1;                  // warp parity: 0 -> A+, 1 -> A-
    const int h   = w >> 1;                 // bc half
    const int lc0 = (lane >> 3) * 8;        // 8 consecutive compacted l
    const int bto = h * 32 + (lane & 7) * 4;
    const int dlt = pw ^ (m & 1);           // actual l = l0 + 2*lc + dlt

    const float* wrow   = weight + ((size_t)m * MDIM + l0 + lr) * KR;
    const u64*   apbase = g_rip + ((size_t)m * KF) * BCN + bc0;
    const u64*   ambase = g_rim + ((size_t)m * KF) * BCN + bc0;

    u64 acc[8][4];
#pragma unroll
    for (int j = 0; j < 8; j++)
#pragma unroll
        for (int i = 0; i < 4; i++) acc[j][i] = 0ull;

    float4 w40, w41;
    auto cpa_tile = [&](int buf, int kb) {
#pragma unroll
        for (int c = 0; c < 4; c++) {
            int chunk = t * 4 + c;          // 0..511
            int kk = chunk >> 5, col = chunk & 31;
            int kg = kb + kk;               // kg <= 95 always
            int bytes = (kg >= klo) ? 16 : 0;   // zero-fill below band
            cpa16(APS + buf * 8192 + kk * 512 + col * 16,
                  apbase + (size_t)kg * BCN + col * 2, bytes);
            cpa16(AMS + buf * 8192 + kk * 512 + col * 16,
                  ambase + (size_t)kg * BCN + col * 2, bytes);
        }
        cpcommit();
    };
    auto ldW = [&](int kb) {
        w40 = *(const float4*)(wrow + kb + kq);
        w41 = *(const float4*)(wrow + kb + kq + 4);
    };
    auto stW = [&](int buf) {
        u32 ws = WS + buf * 4096 + wpar * 128 + wlc * 4;
        sts1(ws + (kq + 0) * 256, w40.x);
        sts1(ws + (kq + 1) * 256, w40.y);
        sts1(ws + (kq + 2) * 256, w40.z);
        sts1(ws + (kq + 3) * 256, w40.w);
        sts1(ws + (kq + 4) * 256, w41.x);
        sts1(ws + (kq + 5) * 256, w41.y);
        sts1(ws + (kq + 6) * 256, w41.z);
        sts1(ws + (kq + 7) * 256, w41.w);
    };

    const u32 AT = pw ? AMS : APS;

    auto compute = [&](int buf) {
        u32 as_ = AT + buf * 8192 + bto * 8;
        u32 ws  = WS + buf * 4096 + pw * 128 + lc0 * 4;
#pragma unroll
        for (int kk = 0; kk < 16; ++kk) {
            u64 a[4];
            lds2(a[0], a[1], as_ + kk * 512);
            lds2(a[2], a[3], as_ + kk * 512 + 16);
            float4 f0 = lds4f(ws + kk * 256);
            float4 f1 = lds4f(ws + kk * 256 + 16);
            const float fw[8] = {f0.x, f0.y, f0.z, f0.w, f1.x, f1.y, f1.z, f1.w};
#pragma unroll
            for (int j = 0; j < 8; j++) {
                u64 ww = pk2(fw[j], fw[j]);
#pragma unroll
                for (int i = 0; i < 4; i++)
                    acc[j][i] = ffma2(a[i], ww, acc[j][i]);
            }
        }
    };

    cpa_tile(0, kb0);
    ldW(kb0);
    stW(0);
    cpwait0();
    __syncthreads();
    for (int ti = 0; ti < nkt; ++ti) {
        int kb = kb0 + ((ti + 1) << 4);
        bool nx = (ti + 1) < nkt;
        if (nx) { cpa_tile((ti + 1) & 1, kb); ldW(kb); }
        compute(ti & 1);
        if (nx) { stW((ti + 1) & 1); cpwait0(); }
        __syncthreads();
    }

    // coalesced staging writes: [m][l][bc]; rows l = l0 + 2*(lc0+j) + dlt
#pragma unroll
    for (int j = 0; j < 8; j++) {
        int l = l0 + 2 * (lc0 + j) + dlt;
        u64* o = g_st + (((size_t)m * MDIM) + l) * BCN + bc0 + bto;
        ulonglong2 w0, w1;
        w0.x = acc[j][0]; w0.y = acc[j][1];
        w1.x = acc[j][2]; w1.y = acc[j][3];
        *(ulonglong2*)o       = w0;
        *(ulonglong2*)(o + 2) = w1;
    }
}

// ---------------------------------------------------------------------------
// Transpose: out[bc][l][m] <- g_st[m][l][bc]; zero for l < m.
// grid = (16 bc-tiles of 64, 6 m-tiles of 32, 192 l), block = 256.
// ---------------------------------------------------------------------------
extern "C" __global__ void __launch_bounds__(256)
sht_transpose(u64* __restrict__ out)
{
    __shared__ u64 smt[32][65];
    const int t   = threadIdx.x;
    const int bc0 = blockIdx.x * 64;
    const int m0  = blockIdx.y * 32;
    const int l   = blockIdx.z;

    const int mr  = t >> 5;            // 0..7
    const int bcc = (t & 31) * 2;      // 0..62
#pragma unroll
    for (int r = 0; r < 4; ++r) {
        int ml = mr + r * 8;
        ulonglong2 v;
        if (l >= m0 + ml)
            v = *(const ulonglong2*)(g_st + (((size_t)(m0 + ml)) * MDIM + l) * BCN + bc0 + bcc);
        else
            v = make_ulonglong2(0ull, 0ull);
        smt[ml][bcc]     = v.x;
        smt[ml][bcc + 1] = v.y;
    }
    __syncthreads();

    const int bcr = t >> 4;            // 0..15
    const int mc  = (t & 15) * 2;      // 0..30
#pragma unroll
    for (int r = 0; r < 4; ++r) {
        int bcl = bcr + r * 16;
        ulonglong2 v;
        v.x = smt[mc][bcl];
        v.y = smt[mc + 1][bcl];
        *(ulonglong2*)(out + (((size_t)(bc0 + bcl)) * MDIM + l) * MDIM + m0 + mc) = v;
    }
}

// ---------------------------------------------------------------------------

extern "C" void kernel_launch(void* const* d_in, const int* in_sizes, int n_in,
                              void* d_out, int out_size)
{
    (void)in_sizes; (void)n_in; (void)out_size;
    const float* x      = (const float*)d_in[0];
    const float* weight = (const float*)d_in[1];
    const float* cosb   = (const float*)d_in[2];
    const float* sinb   = (const float*)d_in[3];

    dim3 gA(16, 96, 3);
    sht_stageA<<<gA, 256>>>(x, cosb, sinb);

    dim3 gB(16, 3, 192);
    sht_stageB<<<gB, 128>>>(weight);

    dim3 gT(16, 6, 192);
    sht_transpose<<<gT, 256>>>((u64*)d_out);
}